// round 2
// baseline (speedup 1.0000x reference)
#include <cuda_runtime.h>
#include <cuda_bf16.h>
#include <cstddef>

// Problem dims
#define BSZ  32
#define SEQ  2048
#define IND  512
#define HID  256
#define MROWS (BSZ * SEQ)          // 65536

// ---------------- scratch (device globals; no allocs allowed) ---------------
__device__ float g_P [BSZ * SEQ * HID];   // fc output (layer0 input, both halves identical)
__device__ float g_Zl[BSZ * SEQ * HID];   // gate pre-activations, ltr
__device__ float g_Zr[BSZ * SEQ * HID];   // gate pre-activations, rtl
__device__ float g_Yl[BSZ * SEQ * HID];   // layer0 ltr output
__device__ float g_Yr[BSZ * SEQ * HID];   // layer0 rtl output (time-unflipped storage)

// ---------------------------------------------------------------------------
// GEMM: C[m,n] = sum_k A[m,k] * W[n,k] + bias[n]
// A: [M,K] row-major, W: [N,K] row-major (i.e. computes A @ W^T), C: [M,N].
// BM=BN=128, BK=16, 8x8 thread tile, 256 threads.
// ---------------------------------------------------------------------------
#define BM 128
#define BN 128
#define BK 16
#define TM 8
#define TN 8

__global__ __launch_bounds__(256) void gemm_tn_bias(
    const float* __restrict__ A,
    const float* __restrict__ W,
    const float* __restrict__ bias,
    float* __restrict__ C,
    int M, int N, int K)
{
    __shared__ __align__(16) float As[BK][BM + 4];
    __shared__ __align__(16) float Ws[BK][BN + 4];

    const int bm = blockIdx.x * BM;
    const int bn = blockIdx.y * BN;
    const int tid = threadIdx.x;
    const int tx = tid & 15;          // N direction
    const int ty = tid >> 4;          // M direction

    // loader mapping: 512 float4 per tile, 2 per thread
    const int l_row  = tid >> 2;            // 0..63
    const int l_col4 = (tid & 3) * 4;       // 0,4,8,12

    float acc[TM][TN];
    #pragma unroll
    for (int i = 0; i < TM; i++)
        #pragma unroll
        for (int j = 0; j < TN; j++) acc[i][j] = 0.f;

    for (int k0 = 0; k0 < K; k0 += BK) {
        #pragma unroll
        for (int r = 0; r < 2; r++) {
            int row = l_row + r * 64;
            float4 v = *reinterpret_cast<const float4*>(
                &A[(size_t)(bm + row) * K + k0 + l_col4]);
            As[l_col4 + 0][row] = v.x;
            As[l_col4 + 1][row] = v.y;
            As[l_col4 + 2][row] = v.z;
            As[l_col4 + 3][row] = v.w;
        }
        #pragma unroll
        for (int r = 0; r < 2; r++) {
            int row = l_row + r * 64;
            float4 v = *reinterpret_cast<const float4*>(
                &W[(size_t)(bn + row) * K + k0 + l_col4]);
            Ws[l_col4 + 0][row] = v.x;
            Ws[l_col4 + 1][row] = v.y;
            Ws[l_col4 + 2][row] = v.z;
            Ws[l_col4 + 3][row] = v.w;
        }
        __syncthreads();

        #pragma unroll
        for (int kk = 0; kk < BK; kk++) {
            float4 a0 = *reinterpret_cast<const float4*>(&As[kk][ty * TM]);
            float4 a1 = *reinterpret_cast<const float4*>(&As[kk][ty * TM + 4]);
            float4 b0 = *reinterpret_cast<const float4*>(&Ws[kk][tx * TN]);
            float4 b1 = *reinterpret_cast<const float4*>(&Ws[kk][tx * TN + 4]);
            float ra[TM] = {a0.x, a0.y, a0.z, a0.w, a1.x, a1.y, a1.z, a1.w};
            float rb[TN] = {b0.x, b0.y, b0.z, b0.w, b1.x, b1.y, b1.z, b1.w};
            #pragma unroll
            for (int i = 0; i < TM; i++)
                #pragma unroll
                for (int j = 0; j < TN; j++)
                    acc[i][j] = fmaf(ra[i], rb[j], acc[i][j]);
        }
        __syncthreads();
    }

    #pragma unroll
    for (int i = 0; i < TM; i++) {
        int m = bm + ty * TM + i;
        #pragma unroll
        for (int j = 0; j < TN; j += 4) {
            int n = bn + tx * TN + j;
            float4 v;
            v.x = acc[i][j + 0] + bias[n + 0];
            v.y = acc[i][j + 1] + bias[n + 1];
            v.z = acc[i][j + 2] + bias[n + 2];
            v.w = acc[i][j + 3] + bias[n + 3];
            *reinterpret_cast<float4*>(&C[(size_t)m * N + n]) = v;
        }
    }
}

// ---------------------------------------------------------------------------
// Elementwise recurrence (both directions in one launch via blockIdx.y).
// h_t = tanh(x_t * (g*h_{t-1} + (1-g)*x_t)),  g = sigmoid(z_t)
// Each thread owns one (b,j) lane; fully independent across lanes.
// dir==1 walks time backward (reads and writes at the original time index,
// which implements flip -> scan -> flip-back exactly).
// ---------------------------------------------------------------------------
__global__ __launch_bounds__(256) void recur2(
    const float* __restrict__ X0, const float* __restrict__ Z0,
    float* __restrict__ Y0, int yld0, int yoff0,
    const float* __restrict__ X1, const float* __restrict__ Z1,
    float* __restrict__ Y1, int yld1, int yoff1)
{
    const int dir = blockIdx.y;
    const float* __restrict__ X = dir ? X1 : X0;
    const float* __restrict__ Z = dir ? Z1 : Z0;
    float* __restrict__ Y       = dir ? Y1 : Y0;
    const int yld  = dir ? yld1  : yld0;
    const int yoff = dir ? yoff1 : yoff0;

    const int g = blockIdx.x * blockDim.x + threadIdx.x;  // 0..8191
    const int b = g >> 8;
    const int j = g & 255;

    const int t0 = dir ? (SEQ - 1) : 0;
    const ptrdiff_t xstep = dir ? -(ptrdiff_t)HID : (ptrdiff_t)HID;
    const ptrdiff_t ystep = dir ? -(ptrdiff_t)yld : (ptrdiff_t)yld;

    const float* xp = X + ((size_t)b * SEQ + t0) * HID + j;
    const float* zp = Z + ((size_t)b * SEQ + t0) * HID + j;
    float*       yp = Y + ((size_t)b * SEQ + t0) * yld + yoff + j;

    float h  = 0.f;
    float xv = *xp;
    float zv = *zp;

    for (int s = 0; s < SEQ; ++s) {
        float xn = 0.f, zn = 0.f;
        if (s + 1 < SEQ) {           // prefetch next step (independent of h)
            xn = xp[xstep];
            zn = zp[xstep];
        }
        float gate  = 1.0f / (1.0f + __expf(-zv));
        float right = fmaf(gate, h - xv, xv);   // g*h + (1-g)*x
        h = tanhf(xv * right);                  // left == x exactly
        *yp = h;
        xp += xstep; zp += xstep; yp += ystep;
        xv = xn; zv = zn;
    }
}

// ---------------------------------------------------------------------------
// Gather final hidden states: h_out[4][32][256]
//  s=0: layer0 ltr final  = Yl0[b, SEQ-1, :]
//  s=1: layer0 rtl final  = Yr0[b, 0, :]
//  s=2: layer1 ltr final  = xx[b, SEQ-1, 0:256]
//  s=3: layer1 rtl final  = xx[b, 0, 256:512]
// ---------------------------------------------------------------------------
__global__ __launch_bounds__(256) void copy_hout(
    const float* __restrict__ Yl0, const float* __restrict__ Yr0,
    const float* __restrict__ xx, float* __restrict__ hout)
{
    int g = blockIdx.x * blockDim.x + threadIdx.x;  // 0..32767
    int j = g & 255;
    int b = (g >> 8) & 31;
    int s = g >> 13;
    float v;
    if      (s == 0) v = Yl0[((size_t)b * SEQ + (SEQ - 1)) * HID + j];
    else if (s == 1) v = Yr0[((size_t)b * SEQ) * HID + j];
    else if (s == 2) v = xx[((size_t)b * SEQ + (SEQ - 1)) * (2 * HID) + j];
    else             v = xx[((size_t)b * SEQ) * (2 * HID) + HID + j];
    hout[g] = v;
}

// ---------------------------------------------------------------------------
extern "C" void kernel_launch(void* const* d_in, const int* in_sizes, int n_in,
                              void* d_out, int out_size)
{
    const float* x    = (const float*)d_in[0];
    const float* W_fc = (const float*)d_in[1];
    const float* b_fc = (const float*)d_in[2];
    // d_in[3] = W1, d_in[4] = b1 : mathematically dead (g1*x + (1-g1)*x == x)
    const float* W2   = (const float*)d_in[5];
    const float* b2   = (const float*)d_in[6];
    float* out = (float*)d_out;

    float *P, *Zl, *Zr, *Yl, *Yr;
    cudaGetSymbolAddress((void**)&P,  g_P);
    cudaGetSymbolAddress((void**)&Zl, g_Zl);
    cudaGetSymbolAddress((void**)&Zr, g_Zr);
    cudaGetSymbolAddress((void**)&Yl, g_Yl);
    cudaGetSymbolAddress((void**)&Yr, g_Yr);

    float* hout = out + (size_t)BSZ * SEQ * 2 * HID;

    dim3 blk(256);

    // 1) fc projection: P = x @ W_fc^T + b_fc   [65536,512]x[512,256]
    {
        dim3 grid(MROWS / BM, HID / BN);
        gemm_tn_bias<<<grid, blk>>>(x, W_fc, b_fc, P, MROWS, HID, IND);
    }

    // 2) layer 0 gates: both directions see identical inputs (duplicated concat),
    //    so one GEMM serves both: Zl = P @ W2[0]^T + b2[0]
    {
        dim3 grid(MROWS / BM, HID / BN);
        gemm_tn_bias<<<grid, blk>>>(P, W2, b2, Zl, MROWS, HID, HID);
    }

    // 3) layer 0 recurrence, both directions concurrently
    {
        dim3 grid(BSZ * HID / 256, 2);
        recur2<<<grid, blk>>>(P, Zl, Yl, HID, 0,
                              P, Zl, Yr, HID, 0);
    }

    // 4) layer 1 gates
    {
        dim3 grid(MROWS / BM, HID / BN);
        gemm_tn_bias<<<grid, blk>>>(Yl, W2 + HID * HID, b2 + HID, Zl, MROWS, HID, HID);
        gemm_tn_bias<<<grid, blk>>>(Yr, W2 + HID * HID, b2 + HID, Zr, MROWS, HID, HID);
    }

    // 5) layer 1 recurrence -> write straight into d_out (xx, feature stride 512)
    {
        dim3 grid(BSZ * HID / 256, 2);
        recur2<<<grid, blk>>>(Yl, Zl, out, 2 * HID, 0,
                              Yr, Zr, out, 2 * HID, HID);
    }

    // 6) final hidden states
    copy_hout<<<BSZ * HID * 4 / 256, blk>>>(Yl, Yr, out, hout);
}

// round 3
// speedup vs baseline: 1.7831x; 1.7831x over previous
#include <cuda_runtime.h>
#include <cuda_bf16.h>
#include <cstddef>

// Problem dims
#define BSZ  32
#define SEQ  2048
#define IND  512
#define HID  256
#define MROWS (BSZ * SEQ)          // 65536
#define NLANE (BSZ * HID)          // 8192 per direction

// ---------------- scratch (device globals; no allocs allowed) ---------------
__device__ float g_P[BSZ * SEQ * HID];        // fc output (layer0 input, halves identical)
__device__ float g_Z[2 * BSZ * SEQ * HID];    // gate pre-activations (both dirs, layer1)
__device__ float g_Y[2 * BSZ * SEQ * HID];    // layer0 outputs: [ltr | rtl]

// ---------------------------------------------------------------------------
// fast HW approximations (sm_75+ MUFU.TANH)
// ---------------------------------------------------------------------------
__device__ __forceinline__ float tanh_fast(float x) {
    float y;
    asm("tanh.approx.f32 %0, %1;" : "=f"(y) : "f"(x));
    return y;
}

// ---------------------------------------------------------------------------
// GEMM: C[m,n] = sum_k A[m,k] * W[n,k] + bias[n]
// ---------------------------------------------------------------------------
#define BM 128
#define BN 128
#define BK 16
#define TM 8
#define TN 8

__global__ __launch_bounds__(256) void gemm_tn_bias(
    const float* __restrict__ A,
    const float* __restrict__ W,
    const float* __restrict__ bias,
    float* __restrict__ C,
    int M, int N, int K)
{
    __shared__ __align__(16) float As[BK][BM + 4];
    __shared__ __align__(16) float Ws[BK][BN + 4];

    const int bm = blockIdx.x * BM;
    const int bn = blockIdx.y * BN;
    const int tid = threadIdx.x;
    const int tx = tid & 15;          // N direction
    const int ty = tid >> 4;          // M direction

    const int l_row  = tid >> 2;            // 0..63
    const int l_col4 = (tid & 3) * 4;       // 0,4,8,12

    float acc[TM][TN];
    #pragma unroll
    for (int i = 0; i < TM; i++)
        #pragma unroll
        for (int j = 0; j < TN; j++) acc[i][j] = 0.f;

    for (int k0 = 0; k0 < K; k0 += BK) {
        #pragma unroll
        for (int r = 0; r < 2; r++) {
            int row = l_row + r * 64;
            float4 v = *reinterpret_cast<const float4*>(
                &A[(size_t)(bm + row) * K + k0 + l_col4]);
            As[l_col4 + 0][row] = v.x;
            As[l_col4 + 1][row] = v.y;
            As[l_col4 + 2][row] = v.z;
            As[l_col4 + 3][row] = v.w;
        }
        #pragma unroll
        for (int r = 0; r < 2; r++) {
            int row = l_row + r * 64;
            float4 v = *reinterpret_cast<const float4*>(
                &W[(size_t)(bn + row) * K + k0 + l_col4]);
            Ws[l_col4 + 0][row] = v.x;
            Ws[l_col4 + 1][row] = v.y;
            Ws[l_col4 + 2][row] = v.z;
            Ws[l_col4 + 3][row] = v.w;
        }
        __syncthreads();

        #pragma unroll
        for (int kk = 0; kk < BK; kk++) {
            float4 a0 = *reinterpret_cast<const float4*>(&As[kk][ty * TM]);
            float4 a1 = *reinterpret_cast<const float4*>(&As[kk][ty * TM + 4]);
            float4 b0 = *reinterpret_cast<const float4*>(&Ws[kk][tx * TN]);
            float4 b1 = *reinterpret_cast<const float4*>(&Ws[kk][tx * TN + 4]);
            float ra[TM] = {a0.x, a0.y, a0.z, a0.w, a1.x, a1.y, a1.z, a1.w};
            float rb[TN] = {b0.x, b0.y, b0.z, b0.w, b1.x, b1.y, b1.z, b1.w};
            #pragma unroll
            for (int i = 0; i < TM; i++)
                #pragma unroll
                for (int j = 0; j < TN; j++)
                    acc[i][j] = fmaf(ra[i], rb[j], acc[i][j]);
        }
        __syncthreads();
    }

    #pragma unroll
    for (int i = 0; i < TM; i++) {
        int m = bm + ty * TM + i;
        #pragma unroll
        for (int j = 0; j < TN; j += 4) {
            int n = bn + tx * TN + j;
            float4 v;
            v.x = acc[i][j + 0] + bias[n + 0];
            v.y = acc[i][j + 1] + bias[n + 1];
            v.z = acc[i][j + 2] + bias[n + 2];
            v.w = acc[i][j + 3] + bias[n + 3];
            *reinterpret_cast<float4*>(&C[(size_t)m * N + n]) = v;
        }
    }
}

// ---------------------------------------------------------------------------
// Recurrence, software-pipelined depth-D register ring.
//   h_t = tanh(x_t * (g*h_{t-1} + (1-g)*x_t)),  g = sigmoid(z_t)
// Dependent chain per step: FFMA + FMUL + MUFU.TANH (~24 cyc).
// Gate math (sigmoid via tanh) + loads run D steps ahead, off the chain.
// ---------------------------------------------------------------------------
#define PD 16   // pipeline depth

__global__ __launch_bounds__(128) void recur2(
    const float* __restrict__ X0, const float* __restrict__ Z0,
    float* __restrict__ Y0, int yld0, int yoff0,
    const float* __restrict__ X1, const float* __restrict__ Z1,
    float* __restrict__ Y1, int yld1, int yoff1)
{
    const int dir = blockIdx.y;
    const float* __restrict__ X = dir ? X1 : X0;
    const float* __restrict__ Z = dir ? Z1 : Z0;
    float* __restrict__ Y       = dir ? Y1 : Y0;
    const int yld  = dir ? yld1  : yld0;
    const int yoff = dir ? yoff1 : yoff0;

    const int g = blockIdx.x * blockDim.x + threadIdx.x;  // 0..8191
    const int b = g >> 8;
    const int j = g & 255;

    const int t0 = dir ? (SEQ - 1) : 0;
    const ptrdiff_t xstep = dir ? -(ptrdiff_t)HID : (ptrdiff_t)HID;
    const ptrdiff_t ystep = dir ? -(ptrdiff_t)yld : (ptrdiff_t)yld;

    const float* xp = X + ((size_t)b * SEQ + t0) * HID + j;
    const float* zp = Z + ((size_t)b * SEQ + t0) * HID + j;
    float*       yp = Y + ((size_t)b * SEQ + t0) * yld + yoff + j;

    float xr[PD], ar[PD], cr[PD];

    // prologue: fill ring for steps 0..PD-1
    #pragma unroll
    for (int d = 0; d < PD; d++) {
        float xv = xp[(ptrdiff_t)d * xstep];
        float zv = zp[(ptrdiff_t)d * xstep];
        float a  = fmaf(tanh_fast(0.5f * zv), 0.5f, 0.5f);   // sigmoid(z)
        xr[d] = xv;
        ar[d] = a;
        cr[d] = fmaf(-a, xv, xv);                            // (1-a)*x
    }

    float h = 0.f;
    #pragma unroll 1
    for (int blk = 0; blk < SEQ / PD; blk++) {
        const int sbase = blk * PD;
        #pragma unroll
        for (int d = 0; d < PD; d++) {
            // consume ring slot d (step sbase+d)
            float t = fmaf(ar[d], h, cr[d]);     // g*h + (1-g)*x
            h = tanh_fast(xr[d] * t);
            *yp = h;
            yp += ystep;
            // prefetch step sbase+d+PD into slot d
            int sp = sbase + d + PD;
            if (sp < SEQ) {
                float xv = xp[(ptrdiff_t)sp * xstep];
                float zv = zp[(ptrdiff_t)sp * xstep];
                float a  = fmaf(tanh_fast(0.5f * zv), 0.5f, 0.5f);
                xr[d] = xv;
                ar[d] = a;
                cr[d] = fmaf(-a, xv, xv);
            }
        }
    }
}

// ---------------------------------------------------------------------------
// Gather final hidden states: h_out[4][32][256]
// ---------------------------------------------------------------------------
__global__ __launch_bounds__(256) void copy_hout(
    const float* __restrict__ Yl0, const float* __restrict__ Yr0,
    const float* __restrict__ xx, float* __restrict__ hout)
{
    int g = blockIdx.x * blockDim.x + threadIdx.x;  // 0..32767
    int j = g & 255;
    int b = (g >> 8) & 31;
    int s = g >> 13;
    float v;
    if      (s == 0) v = Yl0[((size_t)b * SEQ + (SEQ - 1)) * HID + j];
    else if (s == 1) v = Yr0[((size_t)b * SEQ) * HID + j];
    else if (s == 2) v = xx[((size_t)b * SEQ + (SEQ - 1)) * (2 * HID) + j];
    else             v = xx[((size_t)b * SEQ) * (2 * HID) + HID + j];
    hout[g] = v;
}

// ---------------------------------------------------------------------------
extern "C" void kernel_launch(void* const* d_in, const int* in_sizes, int n_in,
                              void* d_out, int out_size)
{
    const float* x    = (const float*)d_in[0];
    const float* W_fc = (const float*)d_in[1];
    const float* b_fc = (const float*)d_in[2];
    // d_in[3] = W1, d_in[4] = b1 : mathematically dead (g1*x + (1-g1)*x == x)
    const float* W2   = (const float*)d_in[5];
    const float* b2   = (const float*)d_in[6];
    float* out = (float*)d_out;

    float *P, *Zb, *Yb;
    cudaGetSymbolAddress((void**)&P,  g_P);
    cudaGetSymbolAddress((void**)&Zb, g_Z);
    cudaGetSymbolAddress((void**)&Yb, g_Y);

    float* Yl = Yb;
    float* Yr = Yb + (size_t)BSZ * SEQ * HID;
    float* Zl = Zb;
    float* Zr = Zb + (size_t)BSZ * SEQ * HID;

    float* hout = out + (size_t)BSZ * SEQ * 2 * HID;

    // 1) fc projection: P = x @ W_fc^T + b_fc   [65536,512]x[512,256]
    {
        dim3 grid(MROWS / BM, HID / BN);
        gemm_tn_bias<<<grid, 256>>>(x, W_fc, b_fc, P, MROWS, HID, IND);
    }

    // 2) layer 0 gates (one GEMM serves both directions: identical inputs)
    {
        dim3 grid(MROWS / BM, HID / BN);
        gemm_tn_bias<<<grid, 256>>>(P, W2, b2, Zl, MROWS, HID, HID);
    }

    // 3) layer 0 recurrence, both directions concurrently
    {
        dim3 grid(NLANE / 128, 2);
        recur2<<<grid, 128>>>(P, Zl, Yl, HID, 0,
                              P, Zl, Yr, HID, 0);
    }

    // 4) layer 1 gates: single GEMM over [2*65536, 256] (Yl|Yr contiguous)
    {
        dim3 grid(2 * MROWS / BM, HID / BN);
        gemm_tn_bias<<<grid, 256>>>(Yb, W2 + HID * HID, b2 + HID, Zb,
                                    2 * MROWS, HID, HID);
    }

    // 5) layer 1 recurrence -> write straight into d_out (xx, feature stride 512)
    {
        dim3 grid(NLANE / 128, 2);
        recur2<<<grid, 128>>>(Yl, Zl, out, 2 * HID, 0,
                              Yr, Zr, out, 2 * HID, HID);
    }

    // 6) final hidden states
    copy_hout<<<BSZ * HID * 4 / 256, 256>>>(Yl, Yr, out, hout);
}

// round 4
// speedup vs baseline: 2.5305x; 1.4192x over previous
#include <cuda_runtime.h>
#include <cuda_bf16.h>
#include <cstddef>

// Problem dims
#define BSZ  32
#define SEQ  2048
#define IND  512
#define HID  256
#define MROWS (BSZ * SEQ)          // 65536
#define NLANE (BSZ * HID)          // 8192 per direction

// ---------------- scratch (device globals; no allocs allowed) ---------------
__device__ float g_P[BSZ * SEQ * HID];        // fc output (layer0 input, halves identical)
__device__ float g_Z[2 * BSZ * SEQ * HID];    // gates sigma(z) (both dirs for layer1)
__device__ float g_Y[2 * BSZ * SEQ * HID];    // layer0 outputs: [ltr | rtl]

__device__ __forceinline__ float tanh_fast(float x) {
    float y;
    asm("tanh.approx.f32 %0, %1;" : "=f"(y) : "f"(x));
    return y;
}

// ---------------------------------------------------------------------------
// GEMM: C[m,n] = sum_k A[m,k] * W[n,k] + bias[n];  act!=0 -> store sigmoid().
// Register-prefetch of next k-tile to hide global latency.
// ---------------------------------------------------------------------------
#define BM 128
#define BN 128
#define BK 16
#define TM 8
#define TN 8

__global__ __launch_bounds__(256) void gemm_tn_bias(
    const float* __restrict__ A,
    const float* __restrict__ W,
    const float* __restrict__ bias,
    float* __restrict__ C,
    int M, int N, int K, int act)
{
    __shared__ __align__(16) float As[BK][BM + 4];
    __shared__ __align__(16) float Ws[BK][BN + 4];

    const int bm = blockIdx.x * BM;
    const int bn = blockIdx.y * BN;
    const int tid = threadIdx.x;
    const int tx = tid & 15;          // N direction
    const int ty = tid >> 4;          // M direction

    const int l_row  = tid >> 2;            // 0..63
    const int l_col4 = (tid & 3) * 4;       // 0,4,8,12

    const float* Aptr0 = &A[(size_t)(bm + l_row) * K + l_col4];
    const float* Aptr1 = &A[(size_t)(bm + l_row + 64) * K + l_col4];
    const float* Wptr0 = &W[(size_t)(bn + l_row) * K + l_col4];
    const float* Wptr1 = &W[(size_t)(bn + l_row + 64) * K + l_col4];

    float acc[TM][TN];
    #pragma unroll
    for (int i = 0; i < TM; i++)
        #pragma unroll
        for (int j = 0; j < TN; j++) acc[i][j] = 0.f;

    // preload tile 0
    {
        float4 a0 = *reinterpret_cast<const float4*>(Aptr0);
        float4 a1 = *reinterpret_cast<const float4*>(Aptr1);
        float4 w0 = *reinterpret_cast<const float4*>(Wptr0);
        float4 w1 = *reinterpret_cast<const float4*>(Wptr1);
        As[l_col4+0][l_row]    = a0.x; As[l_col4+1][l_row]    = a0.y;
        As[l_col4+2][l_row]    = a0.z; As[l_col4+3][l_row]    = a0.w;
        As[l_col4+0][l_row+64] = a1.x; As[l_col4+1][l_row+64] = a1.y;
        As[l_col4+2][l_row+64] = a1.z; As[l_col4+3][l_row+64] = a1.w;
        Ws[l_col4+0][l_row]    = w0.x; Ws[l_col4+1][l_row]    = w0.y;
        Ws[l_col4+2][l_row]    = w0.z; Ws[l_col4+3][l_row]    = w0.w;
        Ws[l_col4+0][l_row+64] = w1.x; Ws[l_col4+1][l_row+64] = w1.y;
        Ws[l_col4+2][l_row+64] = w1.z; Ws[l_col4+3][l_row+64] = w1.w;
    }
    __syncthreads();

    for (int k0 = 0; k0 < K; k0 += BK) {
        const bool has_next = (k0 + BK) < K;
        float4 nA0, nA1, nW0, nW1;
        if (has_next) {                 // issue early; consumed after compute
            nA0 = *reinterpret_cast<const float4*>(Aptr0 + k0 + BK);
            nA1 = *reinterpret_cast<const float4*>(Aptr1 + k0 + BK);
            nW0 = *reinterpret_cast<const float4*>(Wptr0 + k0 + BK);
            nW1 = *reinterpret_cast<const float4*>(Wptr1 + k0 + BK);
        }

        #pragma unroll
        for (int kk = 0; kk < BK; kk++) {
            float4 a0 = *reinterpret_cast<const float4*>(&As[kk][ty * TM]);
            float4 a1 = *reinterpret_cast<const float4*>(&As[kk][ty * TM + 4]);
            float4 b0 = *reinterpret_cast<const float4*>(&Ws[kk][tx * TN]);
            float4 b1 = *reinterpret_cast<const float4*>(&Ws[kk][tx * TN + 4]);
            float ra[TM] = {a0.x, a0.y, a0.z, a0.w, a1.x, a1.y, a1.z, a1.w};
            float rb[TN] = {b0.x, b0.y, b0.z, b0.w, b1.x, b1.y, b1.z, b1.w};
            #pragma unroll
            for (int i = 0; i < TM; i++)
                #pragma unroll
                for (int j = 0; j < TN; j++)
                    acc[i][j] = fmaf(ra[i], rb[j], acc[i][j]);
        }
        __syncthreads();

        if (has_next) {
            As[l_col4+0][l_row]    = nA0.x; As[l_col4+1][l_row]    = nA0.y;
            As[l_col4+2][l_row]    = nA0.z; As[l_col4+3][l_row]    = nA0.w;
            As[l_col4+0][l_row+64] = nA1.x; As[l_col4+1][l_row+64] = nA1.y;
            As[l_col4+2][l_row+64] = nA1.z; As[l_col4+3][l_row+64] = nA1.w;
            Ws[l_col4+0][l_row]    = nW0.x; Ws[l_col4+1][l_row]    = nW0.y;
            Ws[l_col4+2][l_row]    = nW0.z; Ws[l_col4+3][l_row]    = nW0.w;
            Ws[l_col4+0][l_row+64] = nW1.x; Ws[l_col4+1][l_row+64] = nW1.y;
            Ws[l_col4+2][l_row+64] = nW1.z; Ws[l_col4+3][l_row+64] = nW1.w;
            __syncthreads();
        }
    }

    #pragma unroll
    for (int i = 0; i < TM; i++) {
        int m = bm + ty * TM + i;
        #pragma unroll
        for (int j = 0; j < TN; j += 4) {
            int n = bn + tx * TN + j;
            float4 v;
            v.x = acc[i][j + 0] + bias[n + 0];
            v.y = acc[i][j + 1] + bias[n + 1];
            v.z = acc[i][j + 2] + bias[n + 2];
            v.w = acc[i][j + 3] + bias[n + 3];
            if (act) {   // store sigmoid(z) = 0.5*tanh(0.5 z)+0.5
                v.x = fmaf(tanh_fast(0.5f * v.x), 0.5f, 0.5f);
                v.y = fmaf(tanh_fast(0.5f * v.y), 0.5f, 0.5f);
                v.z = fmaf(tanh_fast(0.5f * v.z), 0.5f, 0.5f);
                v.w = fmaf(tanh_fast(0.5f * v.w), 0.5f, 0.5f);
            }
            *reinterpret_cast<float4*>(&C[(size_t)m * N + n]) = v;
        }
    }
}

// ---------------------------------------------------------------------------
// Recurrence: h_t = tanh(x_t * (a*h_{t-1} + (1-a)*x_t)), a = precomputed gate.
// Ring of RAW loaded values (depth PD=32); ALL math at consume time so the
// scoreboard wait lands PD steps after load issue (~770 cyc cover).
// ---------------------------------------------------------------------------
#define PD 32

__global__ __launch_bounds__(64) void recur2(
    const float* __restrict__ X0, const float* __restrict__ A0,
    float* __restrict__ Y0, int yld0, int yoff0,
    const float* __restrict__ X1, const float* __restrict__ A1,
    float* __restrict__ Y1, int yld1, int yoff1)
{
    const int dir = blockIdx.y;
    const float* __restrict__ X = dir ? X1 : X0;
    const float* __restrict__ Agate = dir ? A1 : A0;
    float* __restrict__ Y = dir ? Y1 : Y0;
    const int yld  = dir ? yld1  : yld0;
    const int yoff = dir ? yoff1 : yoff0;

    const int g = blockIdx.x * blockDim.x + threadIdx.x;  // 0..8191
    const int b = g >> 8;
    const int j = g & 255;

    const int t0 = dir ? (SEQ - 1) : 0;
    const ptrdiff_t xstep = dir ? -(ptrdiff_t)HID : (ptrdiff_t)HID;
    const ptrdiff_t ystep = dir ? -(ptrdiff_t)yld : (ptrdiff_t)yld;

    const float* xp = X + ((size_t)b * SEQ + t0) * HID + j;
    const float* ap = Agate + ((size_t)b * SEQ + t0) * HID + j;
    float*       yp = Y + ((size_t)b * SEQ + t0) * yld + yoff + j;

    float xr[PD], ar[PD];

    // prologue: raw loads only
    #pragma unroll
    for (int d = 0; d < PD; d++) {
        xr[d] = xp[(ptrdiff_t)d * xstep];
        ar[d] = ap[(ptrdiff_t)d * xstep];
    }
    const float* xq = xp + (ptrdiff_t)PD * xstep;
    const float* aq = ap + (ptrdiff_t)PD * xstep;

    float h = 0.f;
    #pragma unroll 1
    for (int blk = 0; blk < SEQ / PD - 1; blk++) {
        #pragma unroll
        for (int d = 0; d < PD; d++) {
            float a  = ar[d];
            float xv = xr[d];
            float c  = fmaf(-a, xv, xv);       // (1-a)*x   (off chain)
            float t  = fmaf(a, h, c);          // chain: FFMA
            h = tanh_fast(xv * t);             // chain: FMUL + MUFU
            *yp = h;
            yp += ystep;
            xr[d] = *xq;                       // raw prefetch, no math
            ar[d] = *aq;
            xq += xstep;
            aq += xstep;
        }
    }
    // epilogue block (no prefetch)
    #pragma unroll
    for (int d = 0; d < PD; d++) {
        float a  = ar[d];
        float xv = xr[d];
        float c  = fmaf(-a, xv, xv);
        float t  = fmaf(a, h, c);
        h = tanh_fast(xv * t);
        *yp = h;
        yp += ystep;
    }
}

// ---------------------------------------------------------------------------
// Gather final hidden states: h_out[4][32][256]
// ---------------------------------------------------------------------------
__global__ __launch_bounds__(256) void copy_hout(
    const float* __restrict__ Yl0, const float* __restrict__ Yr0,
    const float* __restrict__ xx, float* __restrict__ hout)
{
    int g = blockIdx.x * blockDim.x + threadIdx.x;  // 0..32767
    int j = g & 255;
    int b = (g >> 8) & 31;
    int s = g >> 13;
    float v;
    if      (s == 0) v = Yl0[((size_t)b * SEQ + (SEQ - 1)) * HID + j];
    else if (s == 1) v = Yr0[((size_t)b * SEQ) * HID + j];
    else if (s == 2) v = xx[((size_t)b * SEQ + (SEQ - 1)) * (2 * HID) + j];
    else             v = xx[((size_t)b * SEQ) * (2 * HID) + HID + j];
    hout[g] = v;
}

// ---------------------------------------------------------------------------
extern "C" void kernel_launch(void* const* d_in, const int* in_sizes, int n_in,
                              void* d_out, int out_size)
{
    const float* x    = (const float*)d_in[0];
    const float* W_fc = (const float*)d_in[1];
    const float* b_fc = (const float*)d_in[2];
    // d_in[3] = W1, d_in[4] = b1 : mathematically dead (g1*x + (1-g1)*x == x)
    const float* W2   = (const float*)d_in[5];
    const float* b2   = (const float*)d_in[6];
    float* out = (float*)d_out;

    float *P, *Zb, *Yb;
    cudaGetSymbolAddress((void**)&P,  g_P);
    cudaGetSymbolAddress((void**)&Zb, g_Z);
    cudaGetSymbolAddress((void**)&Yb, g_Y);

    float* Yl = Yb;
    float* Yr = Yb + (size_t)BSZ * SEQ * HID;
    float* Zl = Zb;
    float* Zr = Zb + (size_t)BSZ * SEQ * HID;

    float* hout = out + (size_t)BSZ * SEQ * 2 * HID;

    // 1) fc projection: P = x @ W_fc^T + b_fc   (no activation)
    {
        dim3 grid(MROWS / BM, HID / BN);
        gemm_tn_bias<<<grid, 256>>>(x, W_fc, b_fc, P, MROWS, HID, IND, 0);
    }

    // 2) layer 0 gates (shared by both directions): store sigmoid directly
    {
        dim3 grid(MROWS / BM, HID / BN);
        gemm_tn_bias<<<grid, 256>>>(P, W2, b2, Zl, MROWS, HID, HID, 1);
    }

    // 3) layer 0 recurrence, both directions concurrently
    {
        dim3 grid(NLANE / 64, 2);
        recur2<<<grid, 64>>>(P, Zl, Yl, HID, 0,
                             P, Zl, Yr, HID, 0);
    }

    // 4) layer 1 gates: one GEMM over [2*MROWS, 256] (Yl|Yr contiguous)
    {
        dim3 grid(2 * MROWS / BM, HID / BN);
        gemm_tn_bias<<<grid, 256>>>(Yb, W2 + HID * HID, b2 + HID, Zb,
                                    2 * MROWS, HID, HID, 1);
    }

    // 5) layer 1 recurrence -> write straight into d_out (feature stride 512)
    {
        dim3 grid(NLANE / 64, 2);
        recur2<<<grid, 64>>>(Yl, Zl, out, 2 * HID, 0,
                             Yr, Zr, out, 2 * HID, HID);
    }

    // 6) final hidden states
    copy_hout<<<BSZ * HID * 4 / 256, 256>>>(Yl, Yr, out, hout);
}

// round 7
// speedup vs baseline: 4.4139x; 1.7443x over previous
#include <cuda_runtime.h>
#include <cuda_bf16.h>
#include <cstdint>
#include <cstddef>

// Problem dims
#define BSZ  32
#define SEQ  2048
#define IND  512
#define HID  256
#define MROWS (BSZ * SEQ)          // 65536
#define NLANE (BSZ * HID)          // 8192 per direction

// ---------------- scratch (device globals; no allocs allowed) ---------------
__device__ float g_P[BSZ * SEQ * HID];        // fc output
__device__ float g_Z[2 * BSZ * SEQ * HID];    // gates sigma(z)
__device__ float g_Y[2 * BSZ * SEQ * HID];    // layer0 outputs [ltr | rtl]

__device__ __forceinline__ float tanh_fast(float x) {
    float y;
    asm("tanh.approx.f32 %0, %1;" : "=f"(y) : "f"(x));
    return y;
}

// split fp32 pair -> packed bf16x2 (hi) + packed bf16x2 (lo residual)
__device__ __forceinline__ void split2(float a, float b, uint32_t& hi, uint32_t& lo) {
    __nv_bfloat16 ha = __float2bfloat16_rn(a);
    __nv_bfloat16 hb = __float2bfloat16_rn(b);
    float ra = a - __bfloat162float(ha);
    float rb = b - __bfloat162float(hb);
    __nv_bfloat162 hh; hh.x = ha; hh.y = hb;
    __nv_bfloat162 ll = __floats2bfloat162_rn(ra, rb);
    hi = *reinterpret_cast<uint32_t*>(&hh);
    lo = *reinterpret_cast<uint32_t*>(&ll);
}

__device__ __forceinline__ void mma16816(
    float c[4], uint32_t a0, uint32_t a1, uint32_t a2, uint32_t a3,
    uint32_t b0, uint32_t b1)
{
    asm volatile(
        "mma.sync.aligned.m16n8k16.row.col.f32.bf16.bf16.f32 "
        "{%0,%1,%2,%3}, {%4,%5,%6,%7}, {%8,%9}, {%0,%1,%2,%3};"
        : "+f"(c[0]), "+f"(c[1]), "+f"(c[2]), "+f"(c[3])
        : "r"(a0), "r"(a1), "r"(a2), "r"(a3), "r"(b0), "r"(b1));
}

// ---------------------------------------------------------------------------
// Tensor-core GEMM via mma.sync, split-bf16 (3 passes, fp32 accum).
// C[m,n] = sum_k A[m,k] * W[n,k] + bias[n]  (N = 256 fixed; grid.y picks 128-col half)
// BM=128, BN=128, BK=32 fp32; 8 warps (4 M x 2 N), warp tile 32x64.
// ---------------------------------------------------------------------------
#define SB 80   // smem row stride in bytes (32 bf16 = 64B, padded to 80 for bank-free LDS)

__global__ __launch_bounds__(256, 2) void gemm_mma(
    const float* __restrict__ A, const float* __restrict__ W,
    const float* __restrict__ bias, float* __restrict__ C,
    int K, int act)
{
    __shared__ __align__(16) char sAh[128 * SB];
    __shared__ __align__(16) char sAl[128 * SB];
    __shared__ __align__(16) char sWh[128 * SB];
    __shared__ __align__(16) char sWl[128 * SB];

    const int tid  = threadIdx.x;
    const int lane = tid & 31;
    const int warp = tid >> 5;
    const int wm = (warp & 3) * 32;     // warp row offset in tile
    const int wn = (warp >> 2) * 64;    // warp col offset in tile
    const int r = lane >> 2;
    const int q = lane & 3;

    const int bm  = blockIdx.x * 128;
    const int bnG = blockIdx.y * 128;   // global col offset (W row offset)

    // loader mapping: 1024 float4 per operand tile, 4 per thread
    // idx -> row = idx>>3, c4 = (idx&7)*4
    float acc[2][8][4];
    #pragma unroll
    for (int mt = 0; mt < 2; mt++)
        #pragma unroll
        for (int nt = 0; nt < 8; nt++)
            #pragma unroll
            for (int e = 0; e < 4; e++) acc[mt][nt][e] = 0.f;

    const int nch = K >> 5;   // BK=32 fp32 per chunk
    for (int c = 0; c < nch; c++) {
        const int k0 = c << 5;

        #pragma unroll
        for (int i = 0; i < 4; i++) {
            int idx = i * 256 + tid;
            int row = idx >> 3;
            int c4  = (idx & 7) * 4;
            float4 va = *reinterpret_cast<const float4*>(
                &A[(size_t)(bm + row) * K + k0 + c4]);
            float4 vw = *reinterpret_cast<const float4*>(
                &W[(size_t)(bnG + row) * K + k0 + c4]);
            uint2 ahi, alo, whi, wlo;
            split2(va.x, va.y, ahi.x, alo.x);
            split2(va.z, va.w, ahi.y, alo.y);
            split2(vw.x, vw.y, whi.x, wlo.x);
            split2(vw.z, vw.w, whi.y, wlo.y);
            int off = row * SB + c4 * 2;
            *reinterpret_cast<uint2*>(sAh + off) = ahi;
            *reinterpret_cast<uint2*>(sAl + off) = alo;
            *reinterpret_cast<uint2*>(sWh + off) = whi;
            *reinterpret_cast<uint2*>(sWl + off) = wlo;
        }
        __syncthreads();

        #pragma unroll
        for (int pass = 0; pass < 3; pass++) {
            const char* At = (pass == 1) ? sAl : sAh;
            const char* Wt = (pass == 2) ? sWl : sWh;
            #pragma unroll
            for (int ks = 0; ks < 2; ks++) {
                const int ko = ks * 32;   // 16 bf16 = 32 bytes
                uint32_t bfr[8][2];
                #pragma unroll
                for (int nt = 0; nt < 8; nt++) {
                    const char* p = Wt + (wn + nt * 8 + r) * SB + q * 4 + ko;
                    bfr[nt][0] = *reinterpret_cast<const uint32_t*>(p);
                    bfr[nt][1] = *reinterpret_cast<const uint32_t*>(p + 16);
                }
                #pragma unroll
                for (int mt = 0; mt < 2; mt++) {
                    const char* p = At + (wm + mt * 16 + r) * SB + q * 4 + ko;
                    uint32_t a0 = *reinterpret_cast<const uint32_t*>(p);
                    uint32_t a1 = *reinterpret_cast<const uint32_t*>(p + 8 * SB);
                    uint32_t a2 = *reinterpret_cast<const uint32_t*>(p + 16);
                    uint32_t a3 = *reinterpret_cast<const uint32_t*>(p + 8 * SB + 16);
                    #pragma unroll
                    for (int nt = 0; nt < 8; nt++)
                        mma16816(acc[mt][nt], a0, a1, a2, a3, bfr[nt][0], bfr[nt][1]);
                }
            }
        }
        __syncthreads();
    }

    // epilogue: bias (+ optional sigmoid), write fp32
    #pragma unroll
    for (int mt = 0; mt < 2; mt++) {
        const int row = bm + wm + mt * 16 + r;
        #pragma unroll
        for (int nt = 0; nt < 8; nt++) {
            const int col = bnG + wn + nt * 8 + q * 2;
            float b0 = bias[col], b1 = bias[col + 1];
            float2 v0, v1;
            v0.x = acc[mt][nt][0] + b0;
            v0.y = acc[mt][nt][1] + b1;
            v1.x = acc[mt][nt][2] + b0;
            v1.y = acc[mt][nt][3] + b1;
            if (act) {   // sigmoid(z) = 0.5*tanh(0.5z)+0.5
                v0.x = fmaf(tanh_fast(0.5f * v0.x), 0.5f, 0.5f);
                v0.y = fmaf(tanh_fast(0.5f * v0.y), 0.5f, 0.5f);
                v1.x = fmaf(tanh_fast(0.5f * v1.x), 0.5f, 0.5f);
                v1.y = fmaf(tanh_fast(0.5f * v1.y), 0.5f, 0.5f);
            }
            *reinterpret_cast<float2*>(&C[(size_t)row * 256 + col]) = v0;
            *reinterpret_cast<float2*>(&C[(size_t)(row + 8) * 256 + col]) = v1;
        }
    }
}

// ---------------------------------------------------------------------------
// Recurrence: ring of raw loads, depth 32 (unchanged from R4).
// ---------------------------------------------------------------------------
#define PD 32

__global__ __launch_bounds__(64) void recur2(
    const float* __restrict__ X0, const float* __restrict__ A0,
    float* __restrict__ Y0, int yld0, int yoff0,
    const float* __restrict__ X1, const float* __restrict__ A1,
    float* __restrict__ Y1, int yld1, int yoff1)
{
    const int dir = blockIdx.y;
    const float* __restrict__ X = dir ? X1 : X0;
    const float* __restrict__ Agate = dir ? A1 : A0;
    float* __restrict__ Y = dir ? Y1 : Y0;
    const int yld  = dir ? yld1  : yld0;
    const int yoff = dir ? yoff1 : yoff0;

    const int g = blockIdx.x * blockDim.x + threadIdx.x;
    const int b = g >> 8;
    const int j = g & 255;

    const int t0 = dir ? (SEQ - 1) : 0;
    const ptrdiff_t xstep = dir ? -(ptrdiff_t)HID : (ptrdiff_t)HID;
    const ptrdiff_t ystep = dir ? -(ptrdiff_t)yld : (ptrdiff_t)yld;

    const float* xp = X + ((size_t)b * SEQ + t0) * HID + j;
    const float* ap = Agate + ((size_t)b * SEQ + t0) * HID + j;
    float*       yp = Y + ((size_t)b * SEQ + t0) * yld + yoff + j;

    float xr[PD], ar[PD];
    #pragma unroll
    for (int d = 0; d < PD; d++) {
        xr[d] = xp[(ptrdiff_t)d * xstep];
        ar[d] = ap[(ptrdiff_t)d * xstep];
    }
    const float* xq = xp + (ptrdiff_t)PD * xstep;
    const float* aq = ap + (ptrdiff_t)PD * xstep;

    float h = 0.f;
    #pragma unroll 1
    for (int blk = 0; blk < SEQ / PD - 1; blk++) {
        #pragma unroll
        for (int d = 0; d < PD; d++) {
            float a  = ar[d];
            float xv = xr[d];
            float c  = fmaf(-a, xv, xv);
            float t  = fmaf(a, h, c);
            h = tanh_fast(xv * t);
            *yp = h;
            yp += ystep;
            xr[d] = *xq;
            ar[d] = *aq;
            xq += xstep;
            aq += xstep;
        }
    }
    #pragma unroll
    for (int d = 0; d < PD; d++) {
        float a  = ar[d];
        float xv = xr[d];
        float c  = fmaf(-a, xv, xv);
        float t  = fmaf(a, h, c);
        h = tanh_fast(xv * t);
        *yp = h;
        yp += ystep;
    }
}

// ---------------------------------------------------------------------------
__global__ __launch_bounds__(256) void copy_hout(
    const float* __restrict__ Yl0, const float* __restrict__ Yr0,
    const float* __restrict__ xx, float* __restrict__ hout)
{
    int g = blockIdx.x * blockDim.x + threadIdx.x;
    int j = g & 255;
    int b = (g >> 8) & 31;
    int s = g >> 13;
    float v;
    if      (s == 0) v = Yl0[((size_t)b * SEQ + (SEQ - 1)) * HID + j];
    else if (s == 1) v = Yr0[((size_t)b * SEQ) * HID + j];
    else if (s == 2) v = xx[((size_t)b * SEQ + (SEQ - 1)) * (2 * HID) + j];
    else             v = xx[((size_t)b * SEQ) * (2 * HID) + HID + j];
    hout[g] = v;
}

// ---------------------------------------------------------------------------
extern "C" void kernel_launch(void* const* d_in, const int* in_sizes, int n_in,
                              void* d_out, int out_size)
{
    const float* x    = (const float*)d_in[0];
    const float* W_fc = (const float*)d_in[1];
    const float* b_fc = (const float*)d_in[2];
    // d_in[3] = W1, d_in[4] = b1 : dead (g1*x + (1-g1)*x == x)
    const float* W2   = (const float*)d_in[5];
    const float* b2   = (const float*)d_in[6];
    float* out = (float*)d_out;

    float *P, *Zb, *Yb;
    cudaGetSymbolAddress((void**)&P,  g_P);
    cudaGetSymbolAddress((void**)&Zb, g_Z);
    cudaGetSymbolAddress((void**)&Yb, g_Y);

    float* Yl = Yb;
    float* Yr = Yb + (size_t)BSZ * SEQ * HID;
    float* Zl = Zb;
    float* Zr = Zb + (size_t)BSZ * SEQ * HID;
    float* hout = out + (size_t)BSZ * SEQ * 2 * HID;

    // 1) fc projection: P = x @ W_fc^T + b_fc   (K=512, no activation)
    {
        dim3 grid(MROWS / 128, 2);
        gemm_mma<<<grid, 256>>>(x, W_fc, b_fc, P, IND, 0);
    }

    // 2) layer 0 gates (shared by both dirs): store sigmoid directly
    {
        dim3 grid(MROWS / 128, 2);
        gemm_mma<<<grid, 256>>>(P, W2, b2, Zl, HID, 1);
    }

    // 3) layer 0 recurrence, both directions concurrently
    {
        dim3 grid(NLANE / 64, 2);
        recur2<<<grid, 64>>>(P, Zl, Yl, HID, 0,
                             P, Zl, Yr, HID, 0);
    }

    // 4) layer 1 gates: one GEMM over [2*MROWS, 256] (Yl|Yr contiguous)
    {
        dim3 grid(2 * MROWS / 128, 2);
        gemm_mma<<<grid, 256>>>(Yb, W2 + HID * HID, b2 + HID, Zb, HID, 1);
    }

    // 5) layer 1 recurrence -> d_out (feature stride 512)
    {
        dim3 grid(NLANE / 64, 2);
        recur2<<<grid, 64>>>(Yl, Zl, out, 2 * HID, 0,
                             Yr, Zr, out, 2 * HID, HID);
    }

    // 6) final hidden states
    copy_hout<<<BSZ * HID * 4 / 256, 256>>>(Yl, Yr, out, hout);
}

// round 10
// speedup vs baseline: 4.4755x; 1.0140x over previous
#include <cuda_runtime.h>
#include <cuda_bf16.h>
#include <cstdint>
#include <cstddef>

// Problem dims
#define BSZ  32
#define SEQ  2048
#define IND  512
#define HID  256
#define MROWS (BSZ * SEQ)          // 65536
#define NLANE (BSZ * HID)          // 8192 per direction

// ---------------- scratch (device globals; no allocs allowed) ---------------
__device__ float g_P[BSZ * SEQ * HID];        // fc output
__device__ float g_Z[2 * BSZ * SEQ * HID];    // gates sigma(z)
__device__ float g_Y[2 * BSZ * SEQ * HID];    // layer0 outputs [ltr | rtl]

__device__ __forceinline__ float tanh_fast(float x) {
    float y;
    asm("tanh.approx.f32 %0, %1;" : "=f"(y) : "f"(x));
    return y;
}

__device__ __forceinline__ uint32_t smem_u32(const void* p) {
    uint32_t a;
    asm("{ .reg .u64 t; cvta.to.shared.u64 t, %1; cvt.u32.u64 %0, t; }"
        : "=r"(a) : "l"(p));
    return a;
}

// split fp32 pair -> packed bf16x2 (hi) + packed bf16x2 (lo residual)
__device__ __forceinline__ void split2(float a, float b, uint32_t& hi, uint32_t& lo) {
    __nv_bfloat16 ha = __float2bfloat16_rn(a);
    __nv_bfloat16 hb = __float2bfloat16_rn(b);
    float ra = a - __bfloat162float(ha);
    float rb = b - __bfloat162float(hb);
    __nv_bfloat162 hh; hh.x = ha; hh.y = hb;
    __nv_bfloat162 ll = __floats2bfloat162_rn(ra, rb);
    hi = *reinterpret_cast<uint32_t*>(&hh);
    lo = *reinterpret_cast<uint32_t*>(&ll);
}

__device__ __forceinline__ void mma16816(
    float c[4], uint32_t a0, uint32_t a1, uint32_t a2, uint32_t a3,
    uint32_t b0, uint32_t b1)
{
    asm volatile(
        "mma.sync.aligned.m16n8k16.row.col.f32.bf16.bf16.f32 "
        "{%0,%1,%2,%3}, {%4,%5,%6,%7}, {%8,%9}, {%0,%1,%2,%3};"
        : "+f"(c[0]), "+f"(c[1]), "+f"(c[2]), "+f"(c[3])
        : "r"(a0), "r"(a1), "r"(a2), "r"(a3), "r"(b0), "r"(b1));
}

#define LDSM_X4(r0, r1, r2, r3, addr) \
    asm volatile("ldmatrix.sync.aligned.m8n8.x4.shared.b16 {%0,%1,%2,%3}, [%4];" \
        : "=r"(r0), "=r"(r1), "=r"(r2), "=r"(r3) : "r"(addr))

// ---------------------------------------------------------------------------
// Tensor-core GEMM via mma.sync + ldmatrix, split-bf16 (3 passes, fp32 accum).
// C[m,n] = sum_k A[m,k] * W[n,k] + bias[n]  (N=256; grid.y picks 128-col half)
// BM=128, BN=128, BK=32 fp32; 8 warps (4 M x 2 N), warp tile 32x64.
// ---------------------------------------------------------------------------
#define SB 80   // smem row stride bytes (64B data + 16B pad -> LDSM conflict-free)

__global__ __launch_bounds__(256, 2) void gemm_mma(
    const float* __restrict__ A, const float* __restrict__ W,
    const float* __restrict__ bias, float* __restrict__ C,
    int K, int act)
{
    __shared__ __align__(16) char sAh[128 * SB];
    __shared__ __align__(16) char sAl[128 * SB];
    __shared__ __align__(16) char sWh[128 * SB];
    __shared__ __align__(16) char sWl[128 * SB];

    const int tid  = threadIdx.x;
    const int lane = tid & 31;
    const int warp = tid >> 5;
    const int wm = (warp & 3) * 32;     // warp row offset
    const int wn = (warp >> 2) * 64;    // warp col offset
    const int r = lane >> 2;
    const int q = lane & 3;

    const int bm  = blockIdx.x * 128;
    const int bnG = blockIdx.y * 128;

    const uint32_t uAh = smem_u32(sAh), uAl = smem_u32(sAl);
    const uint32_t uWh = smem_u32(sWh), uWl = smem_u32(sWl);

    // per-lane LDSM offsets
    // A tiles: a0=rows[0:8)@k, a1=rows[8:16)@k, a2=rows[0:8)@k+16B, a3=rows[8:16)@k+16B
    const uint32_t aoff = (uint32_t)((lane & 15) * SB + ((lane >> 4) << 4));
    // B pairs (nt=2p,2p+1): t0=nt0@k, t1=nt0@k+16, t2=nt1@k, t3=nt1@k+16
    const uint32_t boff = (uint32_t)(((lane & 7) + (lane >> 4) * 8) * SB + ((lane & 8) << 1));

    float acc[2][8][4];
    #pragma unroll
    for (int mt = 0; mt < 2; mt++)
        #pragma unroll
        for (int nt = 0; nt < 8; nt++)
            #pragma unroll
            for (int e = 0; e < 4; e++) acc[mt][nt][e] = 0.f;

    const int nch = K >> 5;
    for (int c = 0; c < nch; c++) {
        const int k0 = c << 5;

        #pragma unroll
        for (int i = 0; i < 4; i++) {
            int idx = i * 256 + tid;
            int row = idx >> 3;
            int c4  = (idx & 7) * 4;
            float4 va = *reinterpret_cast<const float4*>(
                &A[(size_t)(bm + row) * K + k0 + c4]);
            float4 vw = *reinterpret_cast<const float4*>(
                &W[(size_t)(bnG + row) * K + k0 + c4]);
            uint2 ahi, alo, whi, wlo;
            split2(va.x, va.y, ahi.x, alo.x);
            split2(va.z, va.w, ahi.y, alo.y);
            split2(vw.x, vw.y, whi.x, wlo.x);
            split2(vw.z, vw.w, whi.y, wlo.y);
            int off = row * SB + c4 * 2;
            *reinterpret_cast<uint2*>(sAh + off) = ahi;
            *reinterpret_cast<uint2*>(sAl + off) = alo;
            *reinterpret_cast<uint2*>(sWh + off) = whi;
            *reinterpret_cast<uint2*>(sWl + off) = wlo;
        }
        __syncthreads();

        #pragma unroll
        for (int pass = 0; pass < 3; pass++) {
            const uint32_t uAt = (pass == 1) ? uAl : uAh;
            const uint32_t uWt = (pass == 2) ? uWl : uWh;
            const uint32_t aBase = uAt + (uint32_t)(wm * SB) + aoff;
            const uint32_t bBase = uWt + (uint32_t)(wn * SB) + boff;
            #pragma unroll
            for (int ks = 0; ks < 2; ks++) {
                const uint32_t ko = ks * 32;
                uint32_t bfr[8][2];
                #pragma unroll
                for (int p = 0; p < 4; p++) {
                    LDSM_X4(bfr[2*p][0], bfr[2*p][1], bfr[2*p+1][0], bfr[2*p+1][1],
                            bBase + (uint32_t)(p * 16 * SB) + ko);
                }
                #pragma unroll
                for (int mt = 0; mt < 2; mt++) {
                    uint32_t a0, a1, a2, a3;
                    LDSM_X4(a0, a1, a2, a3, aBase + (uint32_t)(mt * 16 * SB) + ko);
                    #pragma unroll
                    for (int nt = 0; nt < 8; nt++)
                        mma16816(acc[mt][nt], a0, a1, a2, a3, bfr[nt][0], bfr[nt][1]);
                }
            }
        }
        __syncthreads();
    }

    // epilogue: bias (+ optional sigmoid), write fp32
    #pragma unroll
    for (int mt = 0; mt < 2; mt++) {
        const int row = bm + wm + mt * 16 + r;
        #pragma unroll
        for (int nt = 0; nt < 8; nt++) {
            const int col = bnG + wn + nt * 8 + q * 2;
            float b0 = bias[col], b1 = bias[col + 1];
            float2 v0, v1;
            v0.x = acc[mt][nt][0] + b0;
            v0.y = acc[mt][nt][1] + b1;
            v1.x = acc[mt][nt][2] + b0;
            v1.y = acc[mt][nt][3] + b1;
            if (act) {   // sigmoid(z) = 0.5*tanh(0.5z)+0.5
                v0.x = fmaf(tanh_fast(0.5f * v0.x), 0.5f, 0.5f);
                v0.y = fmaf(tanh_fast(0.5f * v0.y), 0.5f, 0.5f);
                v1.x = fmaf(tanh_fast(0.5f * v1.x), 0.5f, 0.5f);
                v1.y = fmaf(tanh_fast(0.5f * v1.y), 0.5f, 0.5f);
            }
            *reinterpret_cast<float2*>(&C[(size_t)row * 256 + col]) = v0;
            *reinterpret_cast<float2*>(&C[(size_t)(row + 8) * 256 + col]) = v1;
        }
    }
}

// ---------------------------------------------------------------------------
// Recurrence: ring of raw loads, depth 32. 128-thread blocks -> 128 CTAs
// over both directions = single wave on 148 SMs (no serialization tail).
// ---------------------------------------------------------------------------
#define PD 32

__global__ __launch_bounds__(128) void recur2(
    const float* __restrict__ X0, const float* __restrict__ A0,
    float* __restrict__ Y0, int yld0, int yoff0,
    const float* __restrict__ X1, const float* __restrict__ A1,
    float* __restrict__ Y1, int yld1, int yoff1)
{
    const int dir = blockIdx.y;
    const float* __restrict__ X = dir ? X1 : X0;
    const float* __restrict__ Agate = dir ? A1 : A0;
    float* __restrict__ Y = dir ? Y1 : Y0;
    const int yld  = dir ? yld1  : yld0;
    const int yoff = dir ? yoff1 : yoff0;

    const int g = blockIdx.x * blockDim.x + threadIdx.x;
    const int b = g >> 8;
    const int j = g & 255;

    const int t0 = dir ? (SEQ - 1) : 0;
    const ptrdiff_t xstep = dir ? -(ptrdiff_t)HID : (ptrdiff_t)HID;
    const ptrdiff_t ystep = dir ? -(ptrdiff_t)yld : (ptrdiff_t)yld;

    const float* xp = X + ((size_t)b * SEQ + t0) * HID + j;
    const float* ap = Agate + ((size_t)b * SEQ + t0) * HID + j;
    float*       yp = Y + ((size_t)b * SEQ + t0) * yld + yoff + j;

    float xr[PD], ar[PD];
    #pragma unroll
    for (int d = 0; d < PD; d++) {
        xr[d] = xp[(ptrdiff_t)d * xstep];
        ar[d] = ap[(ptrdiff_t)d * xstep];
    }
    const float* xq = xp + (ptrdiff_t)PD * xstep;
    const float* aq = ap + (ptrdiff_t)PD * xstep;

    float h = 0.f;
    #pragma unroll 1
    for (int blk = 0; blk < SEQ / PD - 1; blk++) {
        #pragma unroll
        for (int d = 0; d < PD; d++) {
            float a  = ar[d];
            float xv = xr[d];
            float c  = fmaf(-a, xv, xv);
            float t  = fmaf(a, h, c);
            h = tanh_fast(xv * t);
            *yp = h;
            yp += ystep;
            xr[d] = *xq;
            ar[d] = *aq;
            xq += xstep;
            aq += xstep;
        }
    }
    #pragma unroll
    for (int d = 0; d < PD; d++) {
        float a  = ar[d];
        float xv = xr[d];
        float c  = fmaf(-a, xv, xv);
        float t  = fmaf(a, h, c);
        h = tanh_fast(xv * t);
        *yp = h;
        yp += ystep;
    }
}

// ---------------------------------------------------------------------------
__global__ __launch_bounds__(256) void copy_hout(
    const float* __restrict__ Yl0, const float* __restrict__ Yr0,
    const float* __restrict__ xx, float* __restrict__ hout)
{
    int g = blockIdx.x * blockDim.x + threadIdx.x;
    int j = g & 255;
    int b = (g >> 8) & 31;
    int s = g >> 13;
    float v;
    if      (s == 0) v = Yl0[((size_t)b * SEQ + (SEQ - 1)) * HID + j];
    else if (s == 1) v = Yr0[((size_t)b * SEQ) * HID + j];
    else if (s == 2) v = xx[((size_t)b * SEQ + (SEQ - 1)) * (2 * HID) + j];
    else             v = xx[((size_t)b * SEQ) * (2 * HID) + HID + j];
    hout[g] = v;
}

// ---------------------------------------------------------------------------
extern "C" void kernel_launch(void* const* d_in, const int* in_sizes, int n_in,
                              void* d_out, int out_size)
{
    const float* x    = (const float*)d_in[0];
    const float* W_fc = (const float*)d_in[1];
    const float* b_fc = (const float*)d_in[2];
    // d_in[3] = W1, d_in[4] = b1 : dead (g1*x + (1-g1)*x == x)
    const float* W2   = (const float*)d_in[5];
    const float* b2   = (const float*)d_in[6];
    float* out = (float*)d_out;

    float *P, *Zb, *Yb;
    cudaGetSymbolAddress((void**)&P,  g_P);
    cudaGetSymbolAddress((void**)&Zb, g_Z);
    cudaGetSymbolAddress((void**)&Yb, g_Y);

    float* Yl = Yb;
    float* Yr = Yb + (size_t)BSZ * SEQ * HID;
    float* Zl = Zb;
    float* Zr = Zb + (size_t)BSZ * SEQ * HID;
    float* hout = out + (size_t)BSZ * SEQ * 2 * HID;

    // 1) fc projection: P = x @ W_fc^T + b_fc   (K=512)
    {
        dim3 grid(MROWS / 128, 2);
        gemm_mma<<<grid, 256>>>(x, W_fc, b_fc, P, IND, 0);
    }

    // 2) layer 0 gates (shared by both dirs): store sigmoid directly
    {
        dim3 grid(MROWS / 128, 2);
        gemm_mma<<<grid, 256>>>(P, W2, b2, Zl, HID, 1);
    }

    // 3) layer 0 recurrence, both directions concurrently (single wave)
    {
        dim3 grid(NLANE / 128, 2);
        recur2<<<grid, 128>>>(P, Zl, Yl, HID, 0,
                              P, Zl, Yr, HID, 0);
    }

    // 4) layer 1 gates: one GEMM over [2*MROWS, 256]
    {
        dim3 grid(2 * MROWS / 128, 2);
        gemm_mma<<<grid, 256>>>(Yb, W2 + HID * HID, b2 + HID, Zb, HID, 1);
    }

    // 5) layer 1 recurrence -> d_out (feature stride 512)
    {
        dim3 grid(NLANE / 128, 2);
        recur2<<<grid, 128>>>(Yl, Zl, out, 2 * HID, 0,
                              Yr, Zr, out, 2 * HID, HID);
    }

    // 6) final hidden states
    copy_hout<<<BSZ * HID * 4 / 256, 256>>>(Yl, Yr, out, hout);
}

// round 11
// speedup vs baseline: 4.6706x; 1.0436x over previous
#include <cuda_runtime.h>
#include <cuda_bf16.h>
#include <cuda_fp16.h>
#include <cstdint>
#include <cstddef>

// Problem dims
#define BSZ  32
#define SEQ  2048
#define IND  512
#define HID  256
#define MROWS (BSZ * SEQ)          // 65536
#define NLANE (BSZ * HID)          // 8192 per direction

// ---------------- scratch (device globals; no allocs allowed) ---------------
// packed element = (bf16_hi << 16) | bf16_lo ; value = hi + lo (~fp32 precise)
__device__ uint32_t g_Pp[MROWS * HID];            // fc output, packed
__device__ uint32_t g_Yp[2 * MROWS * HID];        // layer0 outputs, packed [ltr|rtl]
__device__ __half   g_Zh[2 * MROWS * HID];        // gates sigma(z), fp16
__device__ uint32_t g_W2p[2 * HID * HID];         // W2 packed (both layers)

__device__ __forceinline__ float tanh_fast(float x) {
    float y;
    asm("tanh.approx.f32 %0, %1;" : "=f"(y) : "f"(x));
    return y;
}

__device__ __forceinline__ uint32_t smem_u32(const void* p) {
    uint32_t a;
    asm("{ .reg .u64 t; cvta.to.shared.u64 t, %1; cvt.u32.u64 %0, t; }"
        : "=r"(a) : "l"(p));
    return a;
}

__device__ __forceinline__ uint32_t prmt(uint32_t a, uint32_t b, uint32_t sel) {
    uint32_t r;
    asm("prmt.b32 %0, %1, %2, %3;" : "=r"(r) : "r"(a), "r"(b), "r"(sel));
    return r;
}

// split fp32 pair -> packed bf16x2 (hi) + packed bf16x2 (lo residual)
__device__ __forceinline__ void split2(float a, float b, uint32_t& hi, uint32_t& lo) {
    __nv_bfloat16 ha = __float2bfloat16_rn(a);
    __nv_bfloat16 hb = __float2bfloat16_rn(b);
    float ra = a - __bfloat162float(ha);
    float rb = b - __bfloat162float(hb);
    __nv_bfloat162 hh; hh.x = ha; hh.y = hb;
    __nv_bfloat162 ll = __floats2bfloat162_rn(ra, rb);
    hi = *reinterpret_cast<uint32_t*>(&hh);
    lo = *reinterpret_cast<uint32_t*>(&ll);
}

// pack one float into (hi<<16)|lo
__device__ __forceinline__ uint32_t pack_hl(float v) {
    __nv_bfloat16 hb = __float2bfloat16_rn(v);
    float r = v - __bfloat162float(hb);
    __nv_bfloat16 lb = __float2bfloat16_rn(r);
    return ((uint32_t)*reinterpret_cast<unsigned short*>(&hb) << 16)
         |  (uint32_t)*reinterpret_cast<unsigned short*>(&lb);
}

__device__ __forceinline__ float unpack_hl(uint32_t p) {
    float hi = __uint_as_float(p & 0xFFFF0000u);
    float lo = __uint_as_float(p << 16);
    return hi + lo;
}

__device__ __forceinline__ void mma16816(
    float c[4], uint32_t a0, uint32_t a1, uint32_t a2, uint32_t a3,
    uint32_t b0, uint32_t b1)
{
    asm volatile(
        "mma.sync.aligned.m16n8k16.row.col.f32.bf16.bf16.f32 "
        "{%0,%1,%2,%3}, {%4,%5,%6,%7}, {%8,%9}, {%0,%1,%2,%3};"
        : "+f"(c[0]), "+f"(c[1]), "+f"(c[2]), "+f"(c[3])
        : "r"(a0), "r"(a1), "r"(a2), "r"(a3), "r"(b0), "r"(b1));
}

#define LDSM_X4(r0, r1, r2, r3, addr) \
    asm volatile("ldmatrix.sync.aligned.m8n8.x4.shared.b16 {%0,%1,%2,%3}, [%4];" \
        : "=r"(r0), "=r"(r1), "=r"(r2), "=r"(r3) : "r"(addr))

#define SB 80   // smem row stride bytes (64B data + 16B pad)

// ===========================================================================
// Shared GEMM core pieces (BM=128, BN=128, BK=32; 8 warps, warp tile 32x64)
// ===========================================================================
struct GemmCtx {
    uint32_t uAh, uAl, uWh, uWl;
    uint32_t aoff, boff;
    int wm, wn, r, q;
};

__device__ __forceinline__ void gemm_compute(
    const GemmCtx& g, float acc[2][8][4])
{
    #pragma unroll
    for (int pass = 0; pass < 3; pass++) {
        const uint32_t uAt = (pass == 1) ? g.uAl : g.uAh;
        const uint32_t uWt = (pass == 2) ? g.uWl : g.uWh;
        const uint32_t aBase = uAt + (uint32_t)(g.wm * SB) + g.aoff;
        const uint32_t bBase = uWt + (uint32_t)(g.wn * SB) + g.boff;
        #pragma unroll
        for (int ks = 0; ks < 2; ks++) {
            const uint32_t ko = ks * 32;
            uint32_t bfr[8][2];
            #pragma unroll
            for (int p = 0; p < 4; p++) {
                LDSM_X4(bfr[2*p][0], bfr[2*p][1], bfr[2*p+1][0], bfr[2*p+1][1],
                        bBase + (uint32_t)(p * 16 * SB) + ko);
            }
            #pragma unroll
            for (int mt = 0; mt < 2; mt++) {
                uint32_t a0, a1, a2, a3;
                LDSM_X4(a0, a1, a2, a3, aBase + (uint32_t)(mt * 16 * SB) + ko);
                #pragma unroll
                for (int nt = 0; nt < 8; nt++)
                    mma16816(acc[mt][nt], a0, a1, a2, a3, bfr[nt][0], bfr[nt][1]);
            }
        }
    }
}

// ---------------------------------------------------------------------------
// fc GEMM: fp32 inputs (x, W_fc), split in loader, epilogue packs to u32.
// K = 512. C = packed(x @ W^T + bias).
// ---------------------------------------------------------------------------
__global__ __launch_bounds__(256, 2) void gemm_fc(
    const float* __restrict__ A, const float* __restrict__ W,
    const float* __restrict__ bias, uint32_t* __restrict__ Cp)
{
    __shared__ __align__(16) char sAh[128 * SB];
    __shared__ __align__(16) char sAl[128 * SB];
    __shared__ __align__(16) char sWh[128 * SB];
    __shared__ __align__(16) char sWl[128 * SB];

    const int tid  = threadIdx.x;
    const int lane = tid & 31;
    const int warp = tid >> 5;
    GemmCtx g;
    g.wm = (warp & 3) * 32; g.wn = (warp >> 2) * 64;
    g.r = lane >> 2; g.q = lane & 3;
    g.uAh = smem_u32(sAh); g.uAl = smem_u32(sAl);
    g.uWh = smem_u32(sWh); g.uWl = smem_u32(sWl);
    g.aoff = (uint32_t)((lane & 15) * SB + ((lane >> 4) << 4));
    g.boff = (uint32_t)(((lane & 7) + (lane >> 4) * 8) * SB + ((lane & 8) << 1));

    const int bm  = blockIdx.x * 128;
    const int bnG = blockIdx.y * 128;
    const int K = IND;

    float acc[2][8][4];
    #pragma unroll
    for (int mt = 0; mt < 2; mt++)
        #pragma unroll
        for (int nt = 0; nt < 8; nt++)
            #pragma unroll
            for (int e = 0; e < 4; e++) acc[mt][nt][e] = 0.f;

    for (int c = 0; c < (K >> 5); c++) {
        const int k0 = c << 5;
        #pragma unroll
        for (int i = 0; i < 4; i++) {
            int idx = i * 256 + tid;
            int row = idx >> 3;
            int c4  = (idx & 7) * 4;
            float4 va = *reinterpret_cast<const float4*>(
                &A[(size_t)(bm + row) * K + k0 + c4]);
            float4 vw = *reinterpret_cast<const float4*>(
                &W[(size_t)(bnG + row) * K + k0 + c4]);
            uint2 ahi, alo, whi, wlo;
            split2(va.x, va.y, ahi.x, alo.x);
            split2(va.z, va.w, ahi.y, alo.y);
            split2(vw.x, vw.y, whi.x, wlo.x);
            split2(vw.z, vw.w, whi.y, wlo.y);
            int off = row * SB + c4 * 2;
            *reinterpret_cast<uint2*>(sAh + off) = ahi;
            *reinterpret_cast<uint2*>(sAl + off) = alo;
            *reinterpret_cast<uint2*>(sWh + off) = whi;
            *reinterpret_cast<uint2*>(sWl + off) = wlo;
        }
        __syncthreads();
        gemm_compute(g, acc);
        __syncthreads();
    }

    #pragma unroll
    for (int mt = 0; mt < 2; mt++) {
        const int row = bm + g.wm + mt * 16 + g.r;
        #pragma unroll
        for (int nt = 0; nt < 8; nt++) {
            const int col = bnG + g.wn + nt * 8 + g.q * 2;
            float b0 = bias[col], b1 = bias[col + 1];
            uint2 p0, p1;
            p0.x = pack_hl(acc[mt][nt][0] + b0);
            p0.y = pack_hl(acc[mt][nt][1] + b1);
            p1.x = pack_hl(acc[mt][nt][2] + b0);
            p1.y = pack_hl(acc[mt][nt][3] + b1);
            *reinterpret_cast<uint2*>(&Cp[(size_t)row * 256 + col]) = p0;
            *reinterpret_cast<uint2*>(&Cp[(size_t)(row + 8) * 256 + col]) = p1;
        }
    }
}

// ---------------------------------------------------------------------------
// Gate GEMM: packed u32 inputs (A, W pre-split), K=256 fixed.
// Loader = LDG + PRMT unpack. Epilogue: sigmoid -> fp16 store.
// ---------------------------------------------------------------------------
__global__ __launch_bounds__(256, 2) void gemm_gate(
    const uint32_t* __restrict__ Ap, const uint32_t* __restrict__ Wp,
    const float* __restrict__ bias, __half* __restrict__ Ch)
{
    __shared__ __align__(16) char sAh[128 * SB];
    __shared__ __align__(16) char sAl[128 * SB];
    __shared__ __align__(16) char sWh[128 * SB];
    __shared__ __align__(16) char sWl[128 * SB];

    const int tid  = threadIdx.x;
    const int lane = tid & 31;
    const int warp = tid >> 5;
    GemmCtx g;
    g.wm = (warp & 3) * 32; g.wn = (warp >> 2) * 64;
    g.r = lane >> 2; g.q = lane & 3;
    g.uAh = smem_u32(sAh); g.uAl = smem_u32(sAl);
    g.uWh = smem_u32(sWh); g.uWl = smem_u32(sWl);
    g.aoff = (uint32_t)((lane & 15) * SB + ((lane >> 4) << 4));
    g.boff = (uint32_t)(((lane & 7) + (lane >> 4) * 8) * SB + ((lane & 8) << 1));

    const int bm  = blockIdx.x * 128;
    const int bnG = blockIdx.y * 128;
    const int K = HID;   // 256

    float acc[2][8][4];
    #pragma unroll
    for (int mt = 0; mt < 2; mt++)
        #pragma unroll
        for (int nt = 0; nt < 8; nt++)
            #pragma unroll
            for (int e = 0; e < 4; e++) acc[mt][nt][e] = 0.f;

    for (int c = 0; c < (K >> 5); c++) {
        const int k0 = c << 5;
        #pragma unroll
        for (int i = 0; i < 4; i++) {
            int idx = i * 256 + tid;
            int row = idx >> 3;
            int c4  = (idx & 7) * 4;
            uint4 va = *reinterpret_cast<const uint4*>(
                &Ap[(size_t)(bm + row) * K + k0 + c4]);
            uint4 vw = *reinterpret_cast<const uint4*>(
                &Wp[(size_t)(bnG + row) * K + k0 + c4]);
            uint2 ahi, alo, whi, wlo;
            ahi.x = prmt(va.x, va.y, 0x7632); alo.x = prmt(va.x, va.y, 0x5410);
            ahi.y = prmt(va.z, va.w, 0x7632); alo.y = prmt(va.z, va.w, 0x5410);
            whi.x = prmt(vw.x, vw.y, 0x7632); wlo.x = prmt(vw.x, vw.y, 0x5410);
            whi.y = prmt(vw.z, vw.w, 0x7632); wlo.y = prmt(vw.z, vw.w, 0x5410);
            int off = row * SB + c4 * 2;
            *reinterpret_cast<uint2*>(sAh + off) = ahi;
            *reinterpret_cast<uint2*>(sAl + off) = alo;
            *reinterpret_cast<uint2*>(sWh + off) = whi;
            *reinterpret_cast<uint2*>(sWl + off) = wlo;
        }
        __syncthreads();
        gemm_compute(g, acc);
        __syncthreads();
    }

    #pragma unroll
    for (int mt = 0; mt < 2; mt++) {
        const int row = bm + g.wm + mt * 16 + g.r;
        #pragma unroll
        for (int nt = 0; nt < 8; nt++) {
            const int col = bnG + g.wn + nt * 8 + g.q * 2;
            float b0 = bias[col], b1 = bias[col + 1];
            float s00 = fmaf(tanh_fast(0.5f * (acc[mt][nt][0] + b0)), 0.5f, 0.5f);
            float s01 = fmaf(tanh_fast(0.5f * (acc[mt][nt][1] + b1)), 0.5f, 0.5f);
            float s10 = fmaf(tanh_fast(0.5f * (acc[mt][nt][2] + b0)), 0.5f, 0.5f);
            float s11 = fmaf(tanh_fast(0.5f * (acc[mt][nt][3] + b1)), 0.5f, 0.5f);
            *reinterpret_cast<__half2*>(&Ch[(size_t)row * 256 + col])
                = __floats2half2_rn(s00, s01);
            *reinterpret_cast<__half2*>(&Ch[(size_t)(row + 8) * 256 + col])
                = __floats2half2_rn(s10, s11);
        }
    }
}

// ---------------------------------------------------------------------------
// W2 prep: split both layers of W2 into packed format.
// ---------------------------------------------------------------------------
__global__ __launch_bounds__(256) void prep_w(const float* __restrict__ W2,
                                              uint32_t* __restrict__ W2p)
{
    int i = blockIdx.x * blockDim.x + threadIdx.x;
    W2p[i] = pack_hl(W2[i]);
}

// ---------------------------------------------------------------------------
// Recurrence: x from packed u32 (hi+lo), gate from fp16; ring depth 32.
// POUT: write packed u32 (layer0) else fp32 (layer1 -> d_out).
// ---------------------------------------------------------------------------
#define PD 32

template <bool POUT>
__global__ __launch_bounds__(128) void recur2(
    const uint32_t* __restrict__ X0, const __half* __restrict__ A0,
    uint32_t* __restrict__ P0, float* __restrict__ F0, int yld0, int yoff0,
    const uint32_t* __restrict__ X1, const __half* __restrict__ A1,
    uint32_t* __restrict__ P1, float* __restrict__ F1, int yld1, int yoff1)
{
    const int dir = blockIdx.y;
    const uint32_t* __restrict__ X = dir ? X1 : X0;
    const __half* __restrict__ Ag  = dir ? A1 : A0;
    uint32_t* __restrict__ Yp = dir ? P1 : P0;
    float*    __restrict__ Yf = dir ? F1 : F0;
    const int yld  = dir ? yld1  : yld0;
    const int yoff = dir ? yoff1 : yoff0;

    const int gg = blockIdx.x * blockDim.x + threadIdx.x;
    const int b = gg >> 8;
    const int j = gg & 255;

    const int t0 = dir ? (SEQ - 1) : 0;
    const ptrdiff_t xstep = dir ? -(ptrdiff_t)HID : (ptrdiff_t)HID;
    const ptrdiff_t ystep = dir ? -(ptrdiff_t)yld : (ptrdiff_t)yld;

    const uint32_t* xp = X + ((size_t)b * SEQ + t0) * HID + j;
    const __half*   ap = Ag + ((size_t)b * SEQ + t0) * HID + j;
    const size_t ybase = (size_t)b * SEQ * yld + (size_t)t0 * yld + yoff + j;
    uint32_t* ypp = POUT ? (Yp + ybase) : nullptr;
    float*    ypf = POUT ? nullptr : (Yf + ybase);

    uint32_t xr[PD];
    __half   arh[PD];
    #pragma unroll
    for (int d = 0; d < PD; d++) {
        xr[d]  = xp[(ptrdiff_t)d * xstep];
        arh[d] = ap[(ptrdiff_t)d * xstep];
    }
    const uint32_t* xq = xp + (ptrdiff_t)PD * xstep;
    const __half*   aq = ap + (ptrdiff_t)PD * xstep;

    float h = 0.f;
    #pragma unroll 1
    for (int blk = 0; blk < SEQ / PD - 1; blk++) {
        #pragma unroll
        for (int d = 0; d < PD; d++) {
            float xv = unpack_hl(xr[d]);
            float a  = __half2float(arh[d]);
            float c  = fmaf(-a, xv, xv);
            float t  = fmaf(a, h, c);
            h = tanh_fast(xv * t);
            if (POUT) { *ypp = pack_hl(h); ypp += ystep; }
            else      { *ypf = h;          ypf += ystep; }
            xr[d]  = *xq;
            arh[d] = *aq;
            xq += xstep;
            aq += xstep;
        }
    }
    #pragma unroll
    for (int d = 0; d < PD; d++) {
        float xv = unpack_hl(xr[d]);
        float a  = __half2float(arh[d]);
        float c  = fmaf(-a, xv, xv);
        float t  = fmaf(a, h, c);
        h = tanh_fast(xv * t);
        if (POUT) { *ypp = pack_hl(h); ypp += ystep; }
        else      { *ypf = h;          ypf += ystep; }
    }
}

// ---------------------------------------------------------------------------
__global__ __launch_bounds__(256) void copy_hout(
    const uint32_t* __restrict__ Ypl, const uint32_t* __restrict__ Ypr,
    const float* __restrict__ xx, float* __restrict__ hout)
{
    int gg = blockIdx.x * blockDim.x + threadIdx.x;
    int j = gg & 255;
    int b = (gg >> 8) & 31;
    int s = gg >> 13;
    float v;
    if      (s == 0) v = unpack_hl(Ypl[((size_t)b * SEQ + (SEQ - 1)) * HID + j]);
    else if (s == 1) v = unpack_hl(Ypr[((size_t)b * SEQ) * HID + j]);
    else if (s == 2) v = xx[((size_t)b * SEQ + (SEQ - 1)) * (2 * HID) + j];
    else             v = xx[((size_t)b * SEQ) * (2 * HID) + HID + j];
    hout[gg] = v;
}

// ---------------------------------------------------------------------------
extern "C" void kernel_launch(void* const* d_in, const int* in_sizes, int n_in,
                              void* d_out, int out_size)
{
    const float* x    = (const float*)d_in[0];
    const float* W_fc = (const float*)d_in[1];
    const float* b_fc = (const float*)d_in[2];
    // d_in[3] = W1, d_in[4] = b1 : dead (g1*x + (1-g1)*x == x)
    const float* W2   = (const float*)d_in[5];
    const float* b2   = (const float*)d_in[6];
    float* out = (float*)d_out;

    uint32_t *Pp, *Yp, *W2p;
    __half *Zh;
    cudaGetSymbolAddress((void**)&Pp,  g_Pp);
    cudaGetSymbolAddress((void**)&Yp,  g_Yp);
    cudaGetSymbolAddress((void**)&Zh,  g_Zh);
    cudaGetSymbolAddress((void**)&W2p, g_W2p);

    uint32_t* Ypl = Yp;
    uint32_t* Ypr = Yp + (size_t)MROWS * HID;
    __half* Zl = Zh;
    __half* Zr = Zh + (size_t)MROWS * HID;
    float* hout = out + (size_t)BSZ * SEQ * 2 * HID;

    // 0) pre-split W2 (both layers) into packed format
    prep_w<<<2 * HID * HID / 256, 256>>>(W2, W2p);

    // 1) fc projection -> packed P
    {
        dim3 grid(MROWS / 128, 2);
        gemm_fc<<<grid, 256>>>(x, W_fc, b_fc, Pp);
    }

    // 2) layer 0 gates (shared by both dirs) -> fp16 sigma
    {
        dim3 grid(MROWS / 128, 2);
        gemm_gate<<<grid, 256>>>(Pp, W2p, b2, Zl);
    }

    // 3) layer 0 recurrence -> packed Y
    {
        dim3 grid(NLANE / 128, 2);
        recur2<true><<<grid, 128>>>(Pp, Zl, Ypl, nullptr, HID, 0,
                                    Pp, Zl, Ypr, nullptr, HID, 0);
    }

    // 4) layer 1 gates: one GEMM over [2*MROWS, 256] (packed Y contiguous)
    {
        dim3 grid(2 * MROWS / 128, 2);
        gemm_gate<<<grid, 256>>>(Yp, W2p + HID * HID, b2 + HID, Zh);
    }

    // 5) layer 1 recurrence -> d_out fp32 (feature stride 512)
    {
        dim3 grid(NLANE / 128, 2);
        recur2<false><<<grid, 128>>>(Ypl, Zl, nullptr, out, 2 * HID, 0,
                                     Ypr, Zr, nullptr, out, 2 * HID, HID);
    }

    // 6) final hidden states
    copy_hout<<<BSZ * HID * 4 / 256, 256>>>(Ypl, Ypr, out, hout);
}